// round 11
// baseline (speedup 1.0000x reference)
#include <cuda_runtime.h>
#include <cuda_fp16.h>
#include <cstdint>

// Shapes (fixed for KANLayer_17265768530645)
#define B_SZ    8192
#define D_IN    512
#define D_OUT   128
#define X_MIN_F (-3.0f)
#define DENOM   6.00000001f
#define SCALE_F (15.0f / DENOM)

// GEMM: y[b,n] = sum_{k'} C[b,k'] * W'[n,k'],  K' = 8704
#define KSTEPS   544          // K'/16
#define NCHUNK   68           // K'/128
#define KHALF    34           // chunks per K-split

// W' as mma B-fragments, CHUNK-MAJOR (32KB per 128-k chunk).
// Index: ((ks*4 + wc)*2 + h)*32 + lane.
__device__ __align__(128) uint4 g_wf[KSTEPS * 4 * 2 * 32];   // 2.2 MB
// K-split partial outputs: [2][B][128] fp32
__device__ __align__(16)  float g_part[2 * (size_t)B_SZ * D_OUT];   // 8.4 MB

// ---------------- PTX helpers (baseline, no 'a'-suffix features) -----------
__device__ __forceinline__ void ldm4(uint32_t* a, uint32_t addr) {
    asm volatile("ldmatrix.sync.aligned.m8n8.x4.shared.b16 {%0,%1,%2,%3}, [%4];"
                 : "=r"(a[0]), "=r"(a[1]), "=r"(a[2]), "=r"(a[3]) : "r"(addr));
}
__device__ __forceinline__ void mma16816(float* c, const uint32_t* a,
                                         uint32_t b0, uint32_t b1) {
    asm volatile(
        "mma.sync.aligned.m16n8k16.row.col.f32.f16.f16.f32 "
        "{%0,%1,%2,%3}, {%4,%5,%6,%7}, {%8,%9}, {%0,%1,%2,%3};"
        : "+f"(c[0]), "+f"(c[1]), "+f"(c[2]), "+f"(c[3])
        : "r"(a[0]), "r"(a[1]), "r"(a[2]), "r"(a[3]), "r"(b0), "r"(b1));
}
__device__ __forceinline__ uint32_t h2u(__half2 h) {
    return *reinterpret_cast<uint32_t*>(&h);
}
__device__ __forceinline__ void cp16(uint32_t saddr, const void* g) {
    asm volatile("cp.async.ca.shared.global [%0], [%1], 16;"
                 :: "r"(saddr), "l"(g));
}
#define CP_COMMIT() asm volatile("cp.async.commit_group;" ::: "memory")
#define CP_WAIT0()  asm volatile("cp.async.wait_group 0;"  ::: "memory")

// ---------------------------------------------------------------------------
// W' prep (validated R7-R10).
// ---------------------------------------------------------------------------
__global__ void kan_wprep(const float* __restrict__ w,    // (128, 512, 16)
                          const float* __restrict__ s)    // (128, 512)
{
    const int wc   = blockIdx.y;
    const int lane = threadIdx.x & 31;
    const int ks   = blockIdx.x * 4 + (threadIdx.x >> 5);

    uint32_t r[8];
    #pragma unroll
    for (int nf = 0; nf < 4; nf++) {
        const int n = wc * 32 + nf * 8 + (lane >> 2);
        #pragma unroll
        for (int h = 0; h < 2; h++) {
            const int k = ks * 16 + (lane & 3) * 2 + h * 8;
            float v0, v1;
            if (ks < 512) {
                v0 = w[(size_t)n * 8192 + k];
                v1 = w[(size_t)n * 8192 + k + 1];
            } else {
                const int kk = k - 8192;
                v0 = s[(size_t)n * 512 + kk];
                v1 = s[(size_t)n * 512 + kk + 1];
            }
            r[nf * 2 + h] = h2u(__floats2half2_rn(v0, v1));
        }
    }
    g_wf[((size_t)(ks * 4 + wc) * 2 + 0) * 32 + lane] = make_uint4(r[0], r[1], r[2], r[3]);
    g_wf[((size_t)(ks * 4 + wc) * 2 + 1) * 32 + lane] = make_uint4(r[4], r[5], r[6], r[7]);
}

// ---------------------------------------------------------------------------
// C-chunk builders. Swizzle: byte(b, cb) = b*256 + (cb ^ ((b&7)<<5)).
// ---------------------------------------------------------------------------
__device__ __forceinline__ void build_spline(char* rb, uint32_t swb,
                                             float xa, float xb, int q)
{
    #pragma unroll
    for (int e = 0; e < 2; e++) {
        const float xx = e ? xb : xa;
        const int il = q * 2 + e;
        float p = fminf(fmaxf((xx - X_MIN_F) * SCALE_F, 0.0f), 15.0f);
        int   k0 = min((int)p, 14);
        float f  = p - (float)k0;
        *reinterpret_cast<uint4*>(rb + ((uint32_t)(il * 32)      ^ swb)) = make_uint4(0,0,0,0);
        *reinterpret_cast<uint4*>(rb + ((uint32_t)(il * 32 + 16) ^ swb)) = make_uint4(0,0,0,0);
        const uint32_t cb = (uint32_t)(il * 32 + k0 * 2);
        *reinterpret_cast<__half*>(rb + (cb ^ swb))       = __float2half_rn(1.0f - f);
        *reinterpret_cast<__half*>(rb + ((cb + 2) ^ swb)) = __float2half_rn(f);
    }
}

__device__ __forceinline__ void build_skip(char* rb, uint32_t swb,
                                           const float* __restrict__ xp, int q)
{
    #pragma unroll
    for (int v = 0; v < 4; v++) {
        float4 f0 = *reinterpret_cast<const float4*>(xp + v * 8);
        float4 f1 = *reinterpret_cast<const float4*>(xp + v * 8 + 4);
        uint4 pk = make_uint4(h2u(__floats2half2_rn(f0.x, f0.y)),
                              h2u(__floats2half2_rn(f0.z, f0.w)),
                              h2u(__floats2half2_rn(f1.x, f1.y)),
                              h2u(__floats2half2_rn(f1.z, f1.w)));
        *reinterpret_cast<uint4*>(rb + ((uint32_t)(q * 64 + v * 16) ^ swb)) = pk;
    }
}

// ---------------------------------------------------------------------------
// Main GEMM: grid (128, 2), block 256. CTA = 64 rows x 128 outs x HALF of K'
// (34 chunks). Warp grid 2(M) x 4(N), warp tile 32x32. B staged via cp.async
// one chunk ahead; C double-buffered. 96KB dyn SMEM -> 2 CTAs/SM.
// ---------------------------------------------------------------------------
__global__ __launch_bounds__(256)
void kan_mma(const float* __restrict__ x)
{
    extern __shared__ __align__(128) char dsm[];
    char* cs = dsm;                    // 2 x 16384
    char* bsm = dsm + 32768;           // 2 x 32768

    const int tid  = threadIdx.x;
    const int lane = tid & 31;
    const int w    = tid >> 5;
    const int wm   = w >> 2;
    const int wc   = w & 3;
    const int bt   = blockIdx.x;       // b-tile 0..127
    const int ksp  = blockIdx.y;       // K-split 0..1
    const int ch0  = ksp * KHALF;

    float acc[2][4][4];
    #pragma unroll
    for (int mf = 0; mf < 2; mf++)
        #pragma unroll
        for (int nf = 0; nf < 4; nf++)
            #pragma unroll
            for (int v = 0; v < 4; v++)
                acc[mf][nf][v] = 0.0f;

    const uint32_t cs32 = (uint32_t)__cvta_generic_to_shared(cs);
    const uint32_t bs32 = (uint32_t)__cvta_generic_to_shared(bsm);
    const int arow  = wm * 32 + (lane & 15);
    const uint32_t swz  = (uint32_t)((lane & 7) << 5);
    const uint32_t aoff = (uint32_t)(arow * 256 + ((lane >> 4) << 4));

    const int bb = tid >> 2, q = tid & 3;
    const uint32_t swb = (uint32_t)((bb & 7) << 5);
    const float* xrow = x + (size_t)(bt * 64 + bb) * 512;

    const uint32_t bwoff = (uint32_t)(wc * 1024 + lane * 16);

    const char* gwb = reinterpret_cast<const char*>(g_wf);
    auto issue_copy = [&](int ch, int buf) {
        const char* src = gwb + (size_t)ch * 32768 + tid * 16;
        uint32_t dst = bs32 + (uint32_t)buf * 32768 + (uint32_t)(tid * 16);
        #pragma unroll
        for (int j = 0; j < 8; j++)
            cp16(dst + j * 4096, src + j * 4096);
        CP_COMMIT();
    };

    // Prologue: stage B chunk ch0, build C chunk ch0 (always spline: ch0<64).
    issue_copy(ch0, 0);
    {
        float2 xv = *reinterpret_cast<const float2*>(xrow + ch0 * 8 + q * 2);
        build_spline(cs + bb * 256, swb, xv.x, xv.y, q);
    }
    CP_WAIT0();
    __syncthreads();

    for (int cl = 0; cl < KHALF; cl++) {
        const int ch  = ch0 + cl;
        const int cur = cl & 1, nxt = cur ^ 1;

        if (cl + 1 < KHALF) issue_copy(ch + 1, nxt);

        float2 xpre = make_float2(0.f, 0.f);
        const bool haveNext  = (cl + 1 < KHALF);
        const bool nextSplin = (ch + 1 < 64);
        if (haveNext && nextSplin)
            xpre = *reinterpret_cast<const float2*>(xrow + (ch + 1) * 8 + q * 2);

        const uint32_t abase0 = cs32 + (uint32_t)cur * 16384 + aoff;
        const uint32_t abase1 = abase0 + 16 * 256;
        const char* bchunk = bsm + cur * 32768;

        uint4 q0 = *reinterpret_cast<const uint4*>(bchunk + bwoff);
        uint4 q1 = *reinterpret_cast<const uint4*>(bchunk + bwoff + 512);

        #pragma unroll
        for (int ksl = 0; ksl < 8; ksl++) {
            const uint4 r0 = q0, r1 = q1;
            if (ksl + 1 < 8) {
                q0 = *reinterpret_cast<const uint4*>(bchunk + (ksl + 1) * 4096 + bwoff);
                q1 = *reinterpret_cast<const uint4*>(bchunk + (ksl + 1) * 4096 + bwoff + 512);
            }
            const uint32_t koff = ((uint32_t)(ksl * 32)) ^ swz;

            uint32_t a[4];
            ldm4(a, abase0 + koff);
            mma16816(acc[0][0], a, r0.x, r0.y);
            mma16816(acc[0][1], a, r0.z, r0.w);
            mma16816(acc[0][2], a, r1.x, r1.y);
            mma16816(acc[0][3], a, r1.z, r1.w);

            ldm4(a, abase1 + koff);
            mma16816(acc[1][0], a, r0.x, r0.y);
            mma16816(acc[1][1], a, r0.z, r0.w);
            mma16816(acc[1][2], a, r1.x, r1.y);
            mma16816(acc[1][3], a, r1.z, r1.w);
        }

        if (haveNext) {
            char* rb = cs + nxt * 16384 + bb * 256;
            if (nextSplin) {
                build_spline(rb, swb, xpre.x, xpre.y, q);
            } else {
                build_skip(rb, swb, xrow + (ch + 1 - 64) * 128 + q * 32, q);
            }
        }
        CP_WAIT0();
        __syncthreads();
    }

    // Epilogue: fp32 partials.
    float* yb = g_part + (size_t)ksp * (B_SZ * D_OUT)
                       + (size_t)(bt * 64 + wm * 32) * 128;
    #pragma unroll
    for (int mf = 0; mf < 2; mf++) {
        const int r0 = mf * 16 + (lane >> 2);
        #pragma unroll
        for (int nf = 0; nf < 4; nf++) {
            const int n0 = wc * 32 + nf * 8 + (lane & 3) * 2;
            *reinterpret_cast<float2*>(yb + (size_t)r0 * 128 + n0) =
                make_float2(acc[mf][nf][0], acc[mf][nf][1]);
            *reinterpret_cast<float2*>(yb + (size_t)(r0 + 8) * 128 + n0) =
                make_float2(acc[mf][nf][2], acc[mf][nf][3]);
        }
    }
}

// ---------------------------------------------------------------------------
// Reduce: y = part0 + part1 + bias. grid=1024, block=256, float4/thread.
// ---------------------------------------------------------------------------
__global__ __launch_bounds__(256)
void kan_reduce(const float* __restrict__ bias, float* __restrict__ y)
{
    const int t = blockIdx.x * 256 + threadIdx.x;      // over B*128/4
    float4 a  = reinterpret_cast<const float4*>(g_part)[t];
    float4 b  = reinterpret_cast<const float4*>(g_part)[t + (B_SZ * D_OUT / 4)];
    float4 bi = reinterpret_cast<const float4*>(bias)[t & 31];
    reinterpret_cast<float4*>(y)[t] =
        make_float4(a.x + b.x + bi.x, a.y + b.y + bi.y,
                    a.z + b.z + bi.z, a.w + b.w + bi.w);
}

// ---------------------------------------------------------------------------
// kernel_launch: inputs per metadata order: x, weights, skip_w, bias
// ---------------------------------------------------------------------------
#define SMEM_DYN (96 * 1024)

extern "C" void kernel_launch(void* const* d_in, const int* in_sizes, int n_in,
                              void* d_out, int out_size)
{
    const float* x    = (const float*)d_in[0];
    const float* w    = (const float*)d_in[1];
    const float* skip = (const float*)d_in[2];
    const float* bias = (const float*)d_in[3];
    float* y = (float*)d_out;

    cudaFuncSetAttribute(kan_mma, cudaFuncAttributeMaxDynamicSharedMemorySize,
                         SMEM_DYN);
    kan_wprep<<<dim3(136, 4), 128>>>(w, skip);
    kan_mma<<<dim3(128, 2), 256, SMEM_DYN>>>(x);
    kan_reduce<<<(B_SZ * D_OUT / 4) / 256, 256>>>(bias, y);
}

// round 12
// speedup vs baseline: 1.2082x; 1.2082x over previous
#include <cuda_runtime.h>
#include <cuda_fp16.h>
#include <cstdint>

// Shapes (fixed for KANLayer_17265768530645)
#define B_SZ    8192
#define D_IN    512
#define D_OUT   128
#define X_MIN_F (-3.0f)
#define DENOM   6.00000001f
#define SCALE_F (15.0f / DENOM)

// GEMM: y[b,n] = sum_{k'} C[b,k'] * W'[n,k'],  K' = 8704
#define KSTEPS   544          // K'/16
#define NCHUNK   68           // K'/128
#define KHALF    34           // chunks per K-split

// W' as mma B-fragments, CHUNK-MAJOR (32KB per 128-k chunk).
// Index: ((ks*4 + wc)*2 + h)*32 + lane.
__device__ __align__(128) uint4 g_wf[KSTEPS * 4 * 2 * 32];   // 2.2 MB
// K-split partial outputs: [2][B][128] fp32
__device__ __align__(16)  float g_part[2 * (size_t)B_SZ * D_OUT];   // 8.4 MB

// ---------------- PTX helpers (baseline, no 'a'-suffix features) -----------
__device__ __forceinline__ void ldm4(uint32_t* a, uint32_t addr) {
    asm volatile("ldmatrix.sync.aligned.m8n8.x4.shared.b16 {%0,%1,%2,%3}, [%4];"
                 : "=r"(a[0]), "=r"(a[1]), "=r"(a[2]), "=r"(a[3]) : "r"(addr));
}
__device__ __forceinline__ void mma16816(float* c, const uint32_t* a,
                                         uint32_t b0, uint32_t b1) {
    asm volatile(
        "mma.sync.aligned.m16n8k16.row.col.f32.f16.f16.f32 "
        "{%0,%1,%2,%3}, {%4,%5,%6,%7}, {%8,%9}, {%0,%1,%2,%3};"
        : "+f"(c[0]), "+f"(c[1]), "+f"(c[2]), "+f"(c[3])
        : "r"(a[0]), "r"(a[1]), "r"(a[2]), "r"(a[3]), "r"(b0), "r"(b1));
}
__device__ __forceinline__ uint32_t h2u(__half2 h) {
    return *reinterpret_cast<uint32_t*>(&h);
}
__device__ __forceinline__ void cp16(uint32_t saddr, const void* g) {
    asm volatile("cp.async.ca.shared.global [%0], [%1], 16;"
                 :: "r"(saddr), "l"(g));
}
#define CP_COMMIT() asm volatile("cp.async.commit_group;" ::: "memory")
#define CP_WAIT0()  asm volatile("cp.async.wait_group 0;"  ::: "memory")

// ---------------------------------------------------------------------------
// W' prep (validated R7-R11).
// ---------------------------------------------------------------------------
__global__ void kan_wprep(const float* __restrict__ w,    // (128, 512, 16)
                          const float* __restrict__ s)    // (128, 512)
{
    const int wc   = blockIdx.y;
    const int lane = threadIdx.x & 31;
    const int ks   = blockIdx.x * 4 + (threadIdx.x >> 5);

    uint32_t r[8];
    #pragma unroll
    for (int nf = 0; nf < 4; nf++) {
        const int n = wc * 32 + nf * 8 + (lane >> 2);
        #pragma unroll
        for (int h = 0; h < 2; h++) {
            const int k = ks * 16 + (lane & 3) * 2 + h * 8;
            float v0, v1;
            if (ks < 512) {
                v0 = w[(size_t)n * 8192 + k];
                v1 = w[(size_t)n * 8192 + k + 1];
            } else {
                const int kk = k - 8192;
                v0 = s[(size_t)n * 512 + kk];
                v1 = s[(size_t)n * 512 + kk + 1];
            }
            r[nf * 2 + h] = h2u(__floats2half2_rn(v0, v1));
        }
    }
    g_wf[((size_t)(ks * 4 + wc) * 2 + 0) * 32 + lane] = make_uint4(r[0], r[1], r[2], r[3]);
    g_wf[((size_t)(ks * 4 + wc) * 2 + 1) * 32 + lane] = make_uint4(r[4], r[5], r[6], r[7]);
}

// ---------------------------------------------------------------------------
// C-chunk builders (128-row tile). Thread: bb = tid>>1 (row), il0 = (tid&1)*4.
// Swizzle: byte(b, cb) = b*256 + (cb ^ ((b&7)<<5)).
// ---------------------------------------------------------------------------
__device__ __forceinline__ void build_spline4(char* rb, uint32_t swb,
                                              float4 xv, int il0)
{
    float xs[4] = {xv.x, xv.y, xv.z, xv.w};
    #pragma unroll
    for (int e = 0; e < 4; e++) {
        const int il = il0 + e;
        float p = fminf(fmaxf((xs[e] - X_MIN_F) * SCALE_F, 0.0f), 15.0f);
        int   k0 = min((int)p, 14);
        float f  = p - (float)k0;
        *reinterpret_cast<uint4*>(rb + ((uint32_t)(il * 32)      ^ swb)) = make_uint4(0,0,0,0);
        *reinterpret_cast<uint4*>(rb + ((uint32_t)(il * 32 + 16) ^ swb)) = make_uint4(0,0,0,0);
        const uint32_t cb = (uint32_t)(il * 32 + k0 * 2);
        *reinterpret_cast<__half*>(rb + (cb ^ swb))       = __float2half_rn(1.0f - f);
        *reinterpret_cast<__half*>(rb + ((cb + 2) ^ swb)) = __float2half_rn(f);
    }
}

__device__ __forceinline__ void build_skip4(char* rb, uint32_t swb,
                                            const float* __restrict__ xp, int il0)
{
    #pragma unroll
    for (int v = 0; v < 8; v++) {
        float4 f0 = *reinterpret_cast<const float4*>(xp + v * 8);
        float4 f1 = *reinterpret_cast<const float4*>(xp + v * 8 + 4);
        uint4 pk = make_uint4(h2u(__floats2half2_rn(f0.x, f0.y)),
                              h2u(__floats2half2_rn(f0.z, f0.w)),
                              h2u(__floats2half2_rn(f1.x, f1.y)),
                              h2u(__floats2half2_rn(f1.z, f1.w)));
        *reinterpret_cast<uint4*>(rb + ((uint32_t)(il0 * 32 + v * 16) ^ swb)) = pk;
    }
}

// ---------------------------------------------------------------------------
// Main GEMM: grid (64, 2), block 256. CTA = 128 rows x 128 outs x K'/2.
// Warp grid 2(M) x 4(N), warp tile 64x32 (4 A-frags, 16 HMMA/warp/kstep).
// B cp.async-staged one chunk ahead; C double-buffered (2x32KB each).
// ---------------------------------------------------------------------------
__global__ __launch_bounds__(256)
void kan_mma(const float* __restrict__ x)
{
    extern __shared__ __align__(128) char dsm[];
    char* cs  = dsm;                    // 2 x 32768 (C: 128 rows x 256B)
    char* bsm = dsm + 65536;            // 2 x 32768 (B chunks)

    const int tid  = threadIdx.x;
    const int lane = tid & 31;
    const int w    = tid >> 5;
    const int wm   = w >> 2;            // 0..1  (64 rows each)
    const int wc   = w & 3;             // 0..3  (32 outs each)
    const int bt   = blockIdx.x;        // b-tile 0..63 (128 rows each)
    const int ksp  = blockIdx.y;        // K-split 0..1
    const int ch0  = ksp * KHALF;

    float acc[4][4][4];                 // [A-frag p][n-frag][4]
    #pragma unroll
    for (int p = 0; p < 4; p++)
        #pragma unroll
        for (int nf = 0; nf < 4; nf++)
            #pragma unroll
            for (int v = 0; v < 4; v++)
                acc[p][nf][v] = 0.0f;

    const uint32_t cs32 = (uint32_t)__cvta_generic_to_shared(cs);
    const uint32_t bs32 = (uint32_t)__cvta_generic_to_shared(bsm);
    const uint32_t swz  = (uint32_t)((lane & 7) << 5);
    // A frag p: rows wm*64 + p*16 + (lane&15)
    const uint32_t aoff = (uint32_t)((wm * 64 + (lane & 15)) * 256 + ((lane >> 4) << 4));

    const int bb  = tid >> 1;           // 0..127 (C row)
    const int il0 = (tid & 1) * 4;      // 4 i-slots per thread
    const uint32_t swb = (uint32_t)((bb & 7) << 5);
    const float* xrow = x + (size_t)(bt * 128 + bb) * 512;

    const uint32_t bwoff = (uint32_t)(wc * 1024 + lane * 16);

    const char* gwb = reinterpret_cast<const char*>(g_wf);
    auto issue_copy = [&](int ch, int buf) {
        const char* src = gwb + (size_t)ch * 32768 + tid * 16;
        uint32_t dst = bs32 + (uint32_t)buf * 32768 + (uint32_t)(tid * 16);
        #pragma unroll
        for (int j = 0; j < 8; j++)
            cp16(dst + j * 4096, src + j * 4096);
        CP_COMMIT();
    };

    // Prologue: stage B chunk ch0, build C chunk ch0 (ch0 < 64: spline).
    issue_copy(ch0, 0);
    {
        float4 xv = *reinterpret_cast<const float4*>(xrow + ch0 * 8 + il0);
        build_spline4(cs + bb * 256, swb, xv, il0);
    }
    CP_WAIT0();
    __syncthreads();

    for (int cl = 0; cl < KHALF; cl++) {
        const int ch  = ch0 + cl;
        const int cur = cl & 1, nxt = cur ^ 1;

        if (cl + 1 < KHALF) issue_copy(ch + 1, nxt);

        float4 xpre = make_float4(0.f, 0.f, 0.f, 0.f);
        const bool haveNext  = (cl + 1 < KHALF);
        const bool nextSplin = (ch + 1 < 64);
        if (haveNext && nextSplin)
            xpre = *reinterpret_cast<const float4*>(xrow + (ch + 1) * 8 + il0);

        const uint32_t abase = cs32 + (uint32_t)cur * 32768 + aoff;
        const char* bchunk = bsm + cur * 32768;

        // Depth-1 k-step pipeline over SMEM-resident B.
        uint4 q0 = *reinterpret_cast<const uint4*>(bchunk + bwoff);
        uint4 q1 = *reinterpret_cast<const uint4*>(bchunk + bwoff + 512);

        #pragma unroll
        for (int ksl = 0; ksl < 8; ksl++) {
            const uint4 r0 = q0, r1 = q1;
            if (ksl + 1 < 8) {
                q0 = *reinterpret_cast<const uint4*>(bchunk + (ksl + 1) * 4096 + bwoff);
                q1 = *reinterpret_cast<const uint4*>(bchunk + (ksl + 1) * 4096 + bwoff + 512);
            }
            const uint32_t koff = ((uint32_t)(ksl * 32)) ^ swz;

            #pragma unroll
            for (int p = 0; p < 4; p++) {
                uint32_t a[4];
                ldm4(a, abase + (uint32_t)p * 4096 + koff);
                mma16816(acc[p][0], a, r0.x, r0.y);
                mma16816(acc[p][1], a, r0.z, r0.w);
                mma16816(acc[p][2], a, r1.x, r1.y);
                mma16816(acc[p][3], a, r1.z, r1.w);
            }
        }

        if (haveNext) {
            char* rb = cs + nxt * 32768 + bb * 256;
            if (nextSplin) {
                build_spline4(rb, swb, xpre, il0);
            } else {
                build_skip4(rb, swb, xrow + (ch + 1 - 64) * 128 + il0 * 16, il0);
            }
        }
        CP_WAIT0();
        __syncthreads();
    }

    // Epilogue: fp32 partials.
    float* yb = g_part + (size_t)ksp * (B_SZ * D_OUT)
                       + (size_t)(bt * 128 + wm * 64) * 128;
    #pragma unroll
    for (int p = 0; p < 4; p++) {
        const int r0 = p * 16 + (lane >> 2);
        #pragma unroll
        for (int nf = 0; nf < 4; nf++) {
            const int n0 = wc * 32 + nf * 8 + (lane & 3) * 2;
            *reinterpret_cast<float2*>(yb + (size_t)r0 * 128 + n0) =
                make_float2(acc[p][nf][0], acc[p][nf][1]);
            *reinterpret_cast<float2*>(yb + (size_t)(r0 + 8) * 128 + n0) =
                make_float2(acc[p][nf][2], acc[p][nf][3]);
        }
    }
}

// ---------------------------------------------------------------------------
// Reduce: y = part0 + part1 + bias. grid=1024, block=256, float4/thread.
// ---------------------------------------------------------------------------
__global__ __launch_bounds__(256)
void kan_reduce(const float* __restrict__ bias, float* __restrict__ y)
{
    const int t = blockIdx.x * 256 + threadIdx.x;      // over B*128/4
    float4 a  = reinterpret_cast<const float4*>(g_part)[t];
    float4 b  = reinterpret_cast<const float4*>(g_part)[t + (B_SZ * D_OUT / 4)];
    float4 bi = reinterpret_cast<const float4*>(bias)[t & 31];
    reinterpret_cast<float4*>(y)[t] =
        make_float4(a.x + b.x + bi.x, a.y + b.y + bi.y,
                    a.z + b.z + bi.z, a.w + b.w + bi.w);
}

// ---------------------------------------------------------------------------
// kernel_launch: inputs per metadata order: x, weights, skip_w, bias
// ---------------------------------------------------------------------------
#define SMEM_DYN (128 * 1024)

extern "C" void kernel_launch(void* const* d_in, const int* in_sizes, int n_in,
                              void* d_out, int out_size)
{
    const float* x    = (const float*)d_in[0];
    const float* w    = (const float*)d_in[1];
    const float* skip = (const float*)d_in[2];
    const float* bias = (const float*)d_in[3];
    float* y = (float*)d_out;

    cudaFuncSetAttribute(kan_mma, cudaFuncAttributeMaxDynamicSharedMemorySize,
                         SMEM_DYN);
    kan_wprep<<<dim3(136, 4), 128>>>(w, skip);
    kan_mma<<<dim3(64, 2), 256, SMEM_DYN>>>(x);
    kan_reduce<<<(B_SZ * D_OUT / 4) / 256, 256>>>(bias, y);
}